// round 1
// baseline (speedup 1.0000x reference)
#include <cuda_runtime.h>

// ARXCell: per batch row b (B = 16384):
//   a2[b]       = dot(iw, itdl[b, 0:2048]) + dot(ow, otdl[b, 0:64]) + bias
//   itdl_new[b] = [ itdl[b, 64:2048], input[b, 0:64] ]        (2048 floats)
//   otdl_new[b] = [ otdl[b, 1:64], a2[b] ]                    (64 floats)
//   outputs[b]  = a2[b]
//
// Output buffer layout (tuple order, flattened):
//   [0, 16384)                          outputs            (B*1*1)
//   [16384, 16384 + 33554432)           itdl_new           (B*2048)
//   [16384 + 33554432, +1048576)        otdl_new           (B*64)
//
// One warp per batch row. itdl is read ONCE per element: each float4 feeds the
// dot product AND is immediately stored to the shifted location (shift = 64
// floats = 16 float4s, so alignment is preserved). Purely HBM-bound; iw/ow are
// tiny and L1-resident.

#define BATCH       16384
#define DI          2048
#define DO          64
#define NIN         64
#define DI4         (DI / 4)     // 512 float4 per row
#define SHIFT4      (NIN / 4)    // 16 float4 shift

__global__ __launch_bounds__(256, 8)
void arx_cell_kernel(const float* __restrict__ input,   // [B, 64]
                     const float* __restrict__ itdl,    // [B, 2048]
                     const float* __restrict__ otdl,    // [B, 64]
                     const float* __restrict__ iw,      // [2048]
                     const float* __restrict__ ow,      // [64]
                     const float* __restrict__ bias,    // [1]
                     float* __restrict__ out_a2,        // [B]
                     float* __restrict__ out_itdl,      // [B, 2048]
                     float* __restrict__ out_otdl)      // [B, 64]
{
    const int gtid = blockIdx.x * blockDim.x + threadIdx.x;
    const int b    = gtid >> 5;          // warp id == batch row
    const int lane = gtid & 31;
    if (b >= BATCH) return;

    const float4* __restrict__ it4  = reinterpret_cast<const float4*>(itdl) + (size_t)b * DI4;
    float4*       __restrict__ nit4 = reinterpret_cast<float4*>(out_itdl)   + (size_t)b * DI4;
    const float4* __restrict__ iw4  = reinterpret_cast<const float4*>(iw);

    float acc = 0.0f;

    // 16 float4 per lane, strided by 32 lanes: fully coalesced, MLP-friendly.
    // Fused: read once -> FMA into acc -> shifted store (drop first 16 f4s).
    #pragma unroll
    for (int j = 0; j < 16; ++j) {
        const int v = j * 32 + lane;          // float4 index in [0, 512)
        float4 x = it4[v];
        float4 w = iw4[v];
        acc = fmaf(x.x, w.x, acc);
        acc = fmaf(x.y, w.y, acc);
        acc = fmaf(x.z, w.z, acc);
        acc = fmaf(x.w, w.w, acc);
        if (v >= SHIFT4) nit4[v - SHIFT4] = x;
    }

    // Append input[b, 0:64] at itdl_new[b, 1984:2048] (float2: 1984 is even).
    {
        const float2* __restrict__ in2 = reinterpret_cast<const float2*>(input) + (size_t)b * (NIN / 2);
        float2 iv = in2[lane];
        float2* __restrict__ dst2 = reinterpret_cast<float2*>(out_itdl + (size_t)b * DI + (DI - NIN));
        dst2[lane] = iv;
    }

    // otdl: 2 floats per lane. Dot with ow + shift-by-1 store.
    float* __restrict__ no = out_otdl + (size_t)b * DO;
    {
        float2 o  = reinterpret_cast<const float2*>(otdl)[(size_t)b * (DO / 2) + lane];
        float2 w2 = reinterpret_cast<const float2*>(ow)[lane];
        acc = fmaf(o.x, w2.x, acc);
        acc = fmaf(o.y, w2.y, acc);
        // otdl_new[t] = otdl[t+1] for t in [0,63): element 2*lane -> slot 2*lane-1,
        // element 2*lane+1 -> slot 2*lane. Covers 0..62; slot 63 gets a2 below.
        if (lane > 0) no[2 * lane - 1] = o.x;
        no[2 * lane] = o.y;
    }

    // Warp butterfly reduction.
    #pragma unroll
    for (int off = 16; off > 0; off >>= 1)
        acc += __shfl_xor_sync(0xffffffffu, acc, off);

    if (lane == 0) {
        float a2 = acc + bias[0];
        out_a2[b] = a2;
        no[DO - 1] = a2;
    }
}

extern "C" void kernel_launch(void* const* d_in, const int* in_sizes, int n_in,
                              void* d_out, int out_size) {
    const float* input = (const float*)d_in[0];   // [16384, 64]
    const float* itdl  = (const float*)d_in[1];   // [16384, 2048, 1]
    const float* otdl  = (const float*)d_in[2];   // [16384, 64, 1]
    const float* iw    = (const float*)d_in[3];   // [1, 2048]
    const float* ow    = (const float*)d_in[4];   // [1, 64]
    const float* bias  = (const float*)d_in[5];   // [1, 1]

    float* out      = (float*)d_out;
    float* out_a2   = out;                                    // 16384
    float* out_itdl = out + BATCH;                            // 16384*2048
    float* out_otdl = out + BATCH + (size_t)BATCH * DI;       // 16384*64

    const int threads = 256;                    // 8 warps -> 8 batch rows/block
    const int blocks  = BATCH / (threads / 32); // 2048

    arx_cell_kernel<<<blocks, threads>>>(input, itdl, otdl, iw, ow, bias,
                                         out_a2, out_itdl, out_otdl);
}

// round 3
// speedup vs baseline: 1.0142x; 1.0142x over previous
#include <cuda_runtime.h>

// ARXCell: per batch row b (B = 16384):
//   a2[b]       = dot(iw, itdl[b, 0:2048]) + dot(ow, otdl[b, 0:64]) + bias
//   itdl_new[b] = [ itdl[b, 64:2048], input[b, 0:64] ]        (2048 floats)
//   otdl_new[b] = [ otdl[b, 1:64], a2[b] ]                    (64 floats)
//   outputs[b]  = a2[b]
//
// Output buffer layout (tuple order, flattened):
//   [0, 16384)                     outputs   (B)
//   [16384, +33554432)             itdl_new  (B*2048)
//   [..., +1048576)                otdl_new  (B*64)
//
// One warp per batch row. itdl read ONCE per element (feeds dot AND shifted
// copy). Streaming (.cs) hints on the big zero-reuse streams; iw stays
// cache-resident. 2-deep software prefetch + relaxed reg budget for MLP.

#define BATCH       16384
#define DI          2048
#define DO          64
#define NIN         64
#define DI4         (DI / 4)     // 512 float4 per row
#define SHIFT4      (NIN / 4)    // 16 float4 shift

__global__ __launch_bounds__(256, 4)
void arx_cell_kernel(const float* __restrict__ input,   // [B, 64]
                     const float* __restrict__ itdl,    // [B, 2048]
                     const float* __restrict__ otdl,    // [B, 64]
                     const float* __restrict__ iw,      // [2048]
                     const float* __restrict__ ow,      // [64]
                     const float* __restrict__ bias,    // [1]
                     float* __restrict__ out_a2,        // [B]
                     float* __restrict__ out_itdl,      // [B, 2048]
                     float* __restrict__ out_otdl)      // [B, 64]
{
    const int gtid = blockIdx.x * blockDim.x + threadIdx.x;
    const int b    = gtid >> 5;          // warp id == batch row
    const int lane = gtid & 31;
    if (b >= BATCH) return;

    const float4* __restrict__ it4  = reinterpret_cast<const float4*>(itdl) + (size_t)b * DI4;
    float4*       __restrict__ nit4 = reinterpret_cast<float4*>(out_itdl)   + (size_t)b * DI4;
    const float4* __restrict__ iw4  = reinterpret_cast<const float4*>(iw);

    // Kick off the small streams early so their latency overlaps the main loop.
    const float2 iv = __ldcs(reinterpret_cast<const float2*>(input) + (size_t)b * (NIN / 2) + lane);
    const float2 ov = __ldcs(reinterpret_cast<const float2*>(otdl)  + (size_t)b * (DO  / 2) + lane);

    float acc = 0.0f;

    // 16 float4 per lane, strided by 32 lanes, 2-deep prefetch.
    float4 x0 = __ldcs(it4 + lane);
    float4 x1 = __ldcs(it4 + 32 + lane);

    #pragma unroll
    for (int j = 0; j < 16; ++j) {
        float4 x = (j & 1) ? x1 : x0;
        if (j + 2 < 16) {
            float4 nx = __ldcs(it4 + (j + 2) * 32 + lane);
            if (j & 1) x1 = nx; else x0 = nx;
        }
        const int v = j * 32 + lane;
        float4 w = iw4[v];                      // L1/L2-resident (8 KB, all warps)
        acc = fmaf(x.x, w.x, acc);
        acc = fmaf(x.y, w.y, acc);
        acc = fmaf(x.z, w.z, acc);
        acc = fmaf(x.w, w.w, acc);
        if (v >= SHIFT4) __stcs(nit4 + (v - SHIFT4), x);
    }

    // Append input[b, 0:64] at itdl_new[b, 1984:2048] (float2-aligned).
    __stcs(reinterpret_cast<float2*>(out_itdl + (size_t)b * DI + (DI - NIN)) + lane, iv);

    // otdl: dot with ow + shift-by-1 store.
    float* __restrict__ no = out_otdl + (size_t)b * DO;
    {
        float2 w2 = reinterpret_cast<const float2*>(ow)[lane];
        acc = fmaf(ov.x, w2.x, acc);
        acc = fmaf(ov.y, w2.y, acc);
        // otdl_new[t] = otdl[t+1]: elem 2*lane -> slot 2*lane-1, elem 2*lane+1 -> slot 2*lane.
        if (lane > 0) __stcs(no + 2 * lane - 1, ov.x);
        __stcs(no + 2 * lane, ov.y);
    }

    // Warp butterfly reduction.
    #pragma unroll
    for (int off = 16; off > 0; off >>= 1)
        acc += __shfl_xor_sync(0xffffffffu, acc, off);

    if (lane == 0) {
        float a2 = acc + bias[0];
        out_a2[b] = a2;
        __stcs(no + (DO - 1), a2);
    }
}

extern "C" void kernel_launch(void* const* d_in, const int* in_sizes, int n_in,
                              void* d_out, int out_size) {
    const float* input = (const float*)d_in[0];   // [16384, 64]
    const float* itdl  = (const float*)d_in[1];   // [16384, 2048, 1]
    const float* otdl  = (const float*)d_in[2];   // [16384, 64, 1]
    const float* iw    = (const float*)d_in[3];   // [1, 2048]
    const float* ow    = (const float*)d_in[4];   // [1, 64]
    const float* bias  = (const float*)d_in[5];   // [1, 1]

    float* out      = (float*)d_out;
    float* out_a2   = out;                                    // 16384
    float* out_itdl = out + BATCH;                            // 16384*2048
    float* out_otdl = out + BATCH + (size_t)BATCH * DI;       // 16384*64

    const int threads = 256;                    // 8 warps -> 8 batch rows/block
    const int blocks  = BATCH / (threads / 32); // 2048

    arx_cell_kernel<<<blocks, threads>>>(input, itdl, otdl, iw, ow, bias,
                                         out_a2, out_itdl, out_otdl);
}